// round 6
// baseline (speedup 1.0000x reference)
#include <cuda_runtime.h>
#include <cstdint>

// DistMap: d[b,i,j] = aa[b,i] + bb[b,j] - 2 * sum_c a[b,c,i]*b[b,c,j]
// a: [B=4, C=64, N=4096] fp32, b: [4, 64, 4096], out: [4, 4096, 4096] fp32
// tf32 mma.sync m16n8k8, CTA 128x128 tile, 4 warps (64x64 warp tiles).
// Each CTA processes JITER=4 consecutive j-tiles at fixed i0:
//   - A-tile loaded once (tf32-converted at STS time)
//   - B-tiles double-buffered via 8B cp.async with logical-n permutation scatter
//     (raw fp32 in smem; cvt.rna at fragment-load time)
//   - epilogue: one float4 STG per thread per group (coalesced)

#define C_DIM 64
#define NN    4096
#define TILE  128
#define JITER 4
#define NTHREADS 128
#define LDT   132   // smem row stride in elems: conflict-free frag LDS

#define SMEM_AS 0
#define TILE_BYTES (64 * LDT * 4)          // 33792
#define SMEM_BS TILE_BYTES                  // two B buffers follow A
#define SMEM_TOTAL (3 * TILE_BYTES)

// ---------------- norms precompute (exact fp32) ----------------

__device__ float g_aa[4 * NN];
__device__ float g_bb[4 * NN];

__global__ void norms_kernel(const float* __restrict__ A, const float* __restrict__ B) {
    int idx = blockIdx.x * blockDim.x + threadIdx.x;    // 0..32767
    int which = idx >> 14;
    int r = idx & 16383;                                 // b*4096 + i
    const float* src = (which ? B : A) + (size_t)(r >> 12) * (C_DIM * NN) + (r & 4095);
    float s = 0.0f;
#pragma unroll
    for (int c = 0; c < C_DIM; c++) { float v = src[(size_t)c * NN]; s += v * v; }
    (which ? g_bb : g_aa)[r] = s;
}

// ---------------- helpers ----------------

__device__ __forceinline__ uint32_t f2tf32(float x) {
    uint32_t u;
    asm("cvt.rna.tf32.f32 %0, %1;" : "=r"(u) : "f"(x));
    return u;
}

__device__ __forceinline__ uint32_t smem_u32(const void* p) {
    uint32_t a;
    asm("{ .reg .u64 t; cvta.to.shared.u64 t, %1; cvt.u32.u64 %0, t; }" : "=r"(a) : "l"(p));
    return a;
}

#define CP_ASYNC8(dst_u32, src_ptr) \
    asm volatile("cp.async.ca.shared.global [%0], [%1], 8;" :: "r"(dst_u32), "l"(src_ptr))
#define CP_COMMIT() asm volatile("cp.async.commit_group;" ::: "memory")
#define CP_WAIT(n)  asm volatile("cp.async.wait_group %0;" :: "n"(n) : "memory")

__device__ __forceinline__ void mma_tf32(float c[4], const uint32_t a[4], const uint32_t b[2]) {
    asm volatile(
        "mma.sync.aligned.m16n8k8.row.col.f32.tf32.tf32.f32 "
        "{%0,%1,%2,%3}, {%4,%5,%6,%7}, {%8,%9}, {%0,%1,%2,%3};"
        : "+f"(c[0]), "+f"(c[1]), "+f"(c[2]), "+f"(c[3])
        : "r"(a[0]), "r"(a[1]), "r"(a[2]), "r"(a[3]), "r"(b[0]), "r"(b[1]));
}

// issue one B tile load: gmem [c][j] float4 -> permuted two 8B cp.async each.
// logical n base for a 4-aligned j offset col4 (within 128-wide tile):
//   nbase = 64*(col4>>6) + 16*((col4>>4)&3) + 2*((col4>>2)&3)
//   (e2=0,1) -> nbase+{0,1}; (e2=2,3) -> nbase+8+{0,1}
__device__ __forceinline__ void issue_b_tile(const float* __restrict__ Bb,
                                             int j0t, uint32_t bs_u32, int tid) {
#pragma unroll
    for (int it = 0; it < 16; it++) {
        int t4   = tid + it * NTHREADS;      // float4 index 0..2047
        int c    = t4 >> 5;
        int col4 = (t4 & 31) << 2;
        const float* src = &Bb[(size_t)c * NN + j0t + col4];
        int nbase = 64 * (col4 >> 6) + 16 * ((col4 >> 4) & 3) + 2 * ((col4 >> 2) & 3);
        uint32_t dst = bs_u32 + (uint32_t)(c * LDT + nbase) * 4u;
        CP_ASYNC8(dst, src);
        CP_ASYNC8(dst + 32u, src + 2);   // nbase+8 elems = +32 bytes
    }
    CP_COMMIT();
}

// ---------------- main kernel ----------------

__global__ __launch_bounds__(NTHREADS, 2)
void distmap_mma_kernel(const float* __restrict__ A,   // [4, 64, 4096]
                        const float* __restrict__ Bm,  // [4, 64, 4096]
                        float* __restrict__ D)         // [4, 4096, 4096]
{
    extern __shared__ __align__(16) char smem[];
    uint32_t* As = (uint32_t*)(smem + SMEM_AS);
    float*    Bs0 = (float*)(smem + SMEM_BS);
    float*    Bs1 = (float*)(smem + SMEM_BS + TILE_BYTES);

    const int tid  = threadIdx.x;
    const int lane = tid & 31;
    const int wid  = tid >> 5;    // 0..3
    const int gid  = lane >> 2;   // 0..7
    const int tig  = lane & 3;    // 0..3
    const int i_w  = (wid >> 1) * 64;
    const int j_w  = (wid & 1) * 64;

    const int b      = blockIdx.z;
    const int i0     = blockIdx.y * TILE;
    const int j0base = blockIdx.x * (TILE * JITER);

    const float* Ab = A  + (size_t)b * C_DIM * NN;
    const float* Bb = Bm + (size_t)b * C_DIM * NN;

    const uint32_t bs0_u32 = smem_u32(Bs0);
    const uint32_t bs1_u32 = smem_u32(Bs1);

    // kick off B tile 0
    issue_b_tile(Bb, j0base, bs0_u32, tid);

    // A tile: LDG float4 -> cvt.rna -> STS (once per CTA)
#pragma unroll
    for (int it = 0; it < 16; it++) {
        int t4   = tid + it * NTHREADS;
        int c    = t4 >> 5;
        int col4 = (t4 & 31) << 2;
        float4 va = *(const float4*)&Ab[(size_t)c * NN + i0 + col4];
        uint4 ua = { f2tf32(va.x), f2tf32(va.y), f2tf32(va.z), f2tf32(va.w) };
        *(uint4*)&As[c * LDT + col4] = ua;
    }

    // aa norms in registers (exact fp32)
    float aav[4][2];
#pragma unroll
    for (int mt = 0; mt < 4; mt++) {
        aav[mt][0] = g_aa[b * NN + i0 + i_w + mt * 16 + gid];
        aav[mt][1] = g_aa[b * NN + i0 + i_w + mt * 16 + 8 + gid];
    }

    float* Dbase = D + (size_t)b * NN * NN;

#pragma unroll
    for (int t = 0; t < JITER; t++) {
        // prefetch next B tile into the other buffer
        if (t + 1 < JITER)
            issue_b_tile(Bb, j0base + (t + 1) * TILE, ((t + 1) & 1) ? bs1_u32 : bs0_u32, tid);

        // wait for B(t); leave the just-issued group in flight
        if (t + 1 < JITER) { CP_WAIT(1); } else { CP_WAIT(0); }
        __syncthreads();

        const float* Bst = (t & 1) ? Bs1 : Bs0;
        const int j0t = j0base + t * TILE;

        float acc[4][8][4];
#pragma unroll
        for (int mt = 0; mt < 4; mt++)
#pragma unroll
            for (int nt = 0; nt < 8; nt++)
#pragma unroll
                for (int e = 0; e < 4; e++) acc[mt][nt][e] = 0.0f;

#pragma unroll
        for (int s = 0; s < 8; s++) {
            const int k0 = s * 8;
            uint32_t afr[4][4];
#pragma unroll
            for (int mt = 0; mt < 4; mt++) {
                int ib = i_w + mt * 16 + gid;
                afr[mt][0] = As[(k0 + tig)     * LDT + ib];
                afr[mt][1] = As[(k0 + tig)     * LDT + ib + 8];
                afr[mt][2] = As[(k0 + 4 + tig) * LDT + ib];
                afr[mt][3] = As[(k0 + 4 + tig) * LDT + ib + 8];
            }
            uint32_t bfr[8][2];
#pragma unroll
            for (int nt = 0; nt < 8; nt++) {
                int jb = j_w + nt * 8 + gid;   // logical n (storage is permuted)
                bfr[nt][0] = f2tf32(Bst[(k0 + tig)     * LDT + jb]);
                bfr[nt][1] = f2tf32(Bst[(k0 + 4 + tig) * LDT + jb]);
            }
#pragma unroll
            for (int mt = 0; mt < 4; mt++)
#pragma unroll
                for (int nt = 0; nt < 8; nt++)
                    mma_tf32(acc[mt][nt], afr[mt], bfr[nt]);
        }

        // epilogue: float4 stores; bb from cached g_bb (exact fp32)
        float4 bbv[4];
#pragma unroll
        for (int np = 0; np < 4; np++)
            bbv[np] = *(const float4*)&g_bb[b * NN + j0t + j_w + np * 16 + 4 * tig];

#pragma unroll
        for (int mt = 0; mt < 4; mt++) {
#pragma unroll
            for (int rh = 0; rh < 2; rh++) {
                int row = i0 + i_w + mt * 16 + rh * 8 + gid;
                float aa = aav[mt][rh];
                float* Drow = &Dbase[(size_t)row * NN + j0t + j_w + 4 * tig];
#pragma unroll
                for (int np = 0; np < 4; np++) {
                    float4 o;
                    o.x = aa + bbv[np].x - 2.0f * acc[mt][2 * np][rh * 2 + 0];
                    o.y = aa + bbv[np].y - 2.0f * acc[mt][2 * np][rh * 2 + 1];
                    o.z = aa + bbv[np].z - 2.0f * acc[mt][2 * np + 1][rh * 2 + 0];
                    o.w = aa + bbv[np].w - 2.0f * acc[mt][2 * np + 1][rh * 2 + 1];
                    *(float4*)&Drow[np * 16] = o;
                }
            }
        }
        __syncthreads();   // protect B buffer reuse (t+2 overwrites buf t&1)
    }
}

// ---------------- launch ----------------

extern "C" void kernel_launch(void* const* d_in, const int* in_sizes, int n_in,
                              void* d_out, int out_size)
{
    const float* a = (const float*)d_in[0];
    const float* b = (const float*)d_in[1];
    float* out = (float*)d_out;

    cudaFuncSetAttribute(distmap_mma_kernel,
                         cudaFuncAttributeMaxDynamicSharedMemorySize, SMEM_TOTAL);

    norms_kernel<<<128, 256>>>(a, b);
    dim3 grid(NN / (TILE * JITER), NN / TILE, 4);   // (8, 32, 4)
    distmap_mma_kernel<<<grid, NTHREADS, SMEM_TOTAL>>>(a, b, out);
}